// round 8
// baseline (speedup 1.0000x reference)
#include <cuda_runtime.h>
#include <cuda_bf16.h>

#define N_BOND   100000
#define D        192
#define N_ETYPES 36
#define E_PER_T  30000
#define BATCH    256
#define N_EDGES  (N_ETYPES * E_PER_T)   // 1,080,000
#define N_SEG    (N_ETYPES * BATCH)     // 9216
#define N_PACKS  (N_EDGES / 4)          // 270000
#define EDGE_BLOCKS ((N_PACKS + 255) / 256)   // 1055

__device__ float g_s[N_BOND];       // per-node scalar projection h[i,:] . W_out
__device__ float g_acc[N_SEG];      // segment accumulators [type*BATCH + graph]
__device__ unsigned int g_ticket;   // edge-block completion counter

// ---------------------------------------------------------------------------
// Kernel 1: s[row] = dot(h[row,:], W_out).  R4-best shape: half-warp per row,
// 4 rows per warp, 6 LDG.128 in flight, one-shot blocks, occ ~86%.
// Side jobs: zero g_acc, reset ticket, L2-prefetch src/seg for edge_kernel.
// ---------------------------------------------------------------------------
__global__ void dot_kernel(const float* __restrict__ h,
                           const float* __restrict__ W,
                           const int*   __restrict__ src,
                           const int*   __restrict__ seg) {
    const int tid = blockIdx.x * blockDim.x + threadIdx.x;
    if (tid == 0) g_ticket = 0u;
    if (tid < N_SEG) g_acc[tid] = 0.f;

    // Warm L2 with the edge index arrays (8.6 MB; L2 = 126 MB).
    {
        const int nlines = (N_EDGES * 4) / 128;   // 33750 lines per array
        if (tid < nlines) {
            asm volatile("prefetch.global.L2 [%0];" ::
                         "l"((const char*)src + (size_t)tid * 128));
            asm volatile("prefetch.global.L2 [%0];" ::
                         "l"((const char*)seg + (size_t)tid * 128));
        }
    }

    const int lane = threadIdx.x & 31;
    const int half = lane >> 4;           // 0 or 1
    const int hl   = lane & 15;           // lane within half-warp
    const int warp = tid >> 5;

    const float4* W4 = reinterpret_cast<const float4*>(W);
    const float4 w0 = W4[hl];
    const float4 w1 = W4[16 + hl];
    const float4 w2 = W4[32 + hl];

    const int row0 = 4 * warp + half;
    const int row1 = row0 + 2;
    if (row0 >= N_BOND) return;

    const float4* p0 = reinterpret_cast<const float4*>(h + (size_t)row0 * D);
    const float4* p1 = reinterpret_cast<const float4*>(h + (size_t)row1 * D);
    float4 a0 = __ldcs(p0 + hl), b0 = __ldcs(p0 + 16 + hl), c0 = __ldcs(p0 + 32 + hl);
    float4 a1 = __ldcs(p1 + hl), b1 = __ldcs(p1 + 16 + hl), c1 = __ldcs(p1 + 32 + hl);

    float acc0 = a0.x * w0.x + a0.y * w0.y + a0.z * w0.z + a0.w * w0.w
               + b0.x * w1.x + b0.y * w1.y + b0.z * w1.z + b0.w * w1.w
               + c0.x * w2.x + c0.y * w2.y + c0.z * w2.z + c0.w * w2.w;
    float acc1 = a1.x * w0.x + a1.y * w0.y + a1.z * w0.z + a1.w * w0.w
               + b1.x * w1.x + b1.y * w1.y + b1.z * w1.z + b1.w * w1.w
               + c1.x * w2.x + c1.y * w2.y + c1.z * w2.z + c1.w * w2.w;

    #pragma unroll
    for (int off = 8; off > 0; off >>= 1) {
        acc0 += __shfl_down_sync(0xffffffffu, acc0, off, 16);
        acc1 += __shfl_down_sync(0xffffffffu, acc1, off, 16);
    }
    if (hl == 0) {
        g_s[row0] = acc0;
        g_s[row1] = acc1;
    }
}

// ---------------------------------------------------------------------------
// Kernel 2: edge gather + segment sum, with the softmax FUSED into the last
// block to finish (atomic ticket + threadfence; ticket reset by dot_kernel
// each replay, so this is deterministic and graph-replay-safe).
// ---------------------------------------------------------------------------
__global__ void edge_kernel(const int* __restrict__ src,
                            const int* __restrict__ seg,
                            const int* __restrict__ mask,
                            float*     __restrict__ out) {
    const int idx  = blockIdx.x * blockDim.x + threadIdx.x;   // pack index
    const int lane = threadIdx.x & 31;

    float val = 0.f;
    int   key = -1;
    if (idx < N_PACKS) {
        const int e0 = idx * 4;
        const int t  = e0 / E_PER_T;     // 4 | 30000: pack never crosses a type
        int4 s4 = reinterpret_cast<const int4*>(src)[idx];
        int4 g4 = reinterpret_cast<const int4*>(seg)[idx];

        float v0 = g_s[s4.x], v1 = g_s[s4.y], v2 = g_s[s4.z], v3 = g_s[s4.w];
        const int kb = t * BATCH;
        int k0 = kb + g4.x, k1 = kb + g4.y, k2 = kb + g4.z, k3 = kb + g4.w;

        float acc = v0; int cur = k0;
        if (k1 == cur) acc += v1; else { atomicAdd(&g_acc[cur], acc); cur = k1; acc = v1; }
        if (k2 == cur) acc += v2; else { atomicAdd(&g_acc[cur], acc); cur = k2; acc = v2; }
        if (k3 == cur) acc += v3; else { atomicAdd(&g_acc[cur], acc); cur = k3; acc = v3; }
        val = acc; key = cur;
    }

    // Warp-level segmented reduction over sorted tail-run keys.
    #pragma unroll
    for (int off = 1; off < 32; off <<= 1) {
        int   okey = __shfl_down_sync(0xffffffffu, key, off);
        float oval = __shfl_down_sync(0xffffffffu, val, off);
        if (lane + off < 32 && okey == key) val += oval;
    }
    int pkey = __shfl_up_sync(0xffffffffu, key, 1);
    if (((lane == 0) || (pkey != key)) && key >= 0) atomicAdd(&g_acc[key], val);

    // ---- last-block-done softmax ----
    __shared__ bool is_last;
    __threadfence();                      // g_acc atomics visible before ticket
    __syncthreads();
    if (threadIdx.x == 0) {
        unsigned int t = atomicAdd(&g_ticket, 1u);
        is_last = (t == (unsigned int)(EDGE_BLOCKS - 1));
    }
    __syncthreads();
    if (!is_last) return;

    // 256 threads: thread b handles graph b. Register-only 3-pass softmax;
    // g_acc/mask reads hit L2 (atomics landed there). __ldcg bypasses L1.
    const int b = threadIdx.x;
    float mx = -3.402823466e38f;
    #pragma unroll
    for (int t = 0; t < N_ETYPES; t++) {
        float x = __ldcg(&g_acc[t * BATCH + b]);      // coalesced across threads
        if (mask[b * N_ETYPES + t] != 0) x = -1e9f;
        mx = fmaxf(mx, x);
    }
    float s = 0.f;
    #pragma unroll
    for (int t = 0; t < N_ETYPES; t++) {
        float x = __ldcg(&g_acc[t * BATCH + b]);
        if (mask[b * N_ETYPES + t] != 0) x = -1e9f;
        s += __expf(x - mx);
    }
    const float inv = 1.f / s;
    #pragma unroll
    for (int t = 0; t < N_ETYPES; t++) {
        float x = __ldcg(&g_acc[t * BATCH + b]);
        if (mask[b * N_ETYPES + t] != 0) x = -1e9f;
        out[b * N_ETYPES + t] = __expf(x - mx) * inv;
    }
}

// ---------------------------------------------------------------------------
extern "C" void kernel_launch(void* const* d_in, const int* in_sizes, int n_in,
                              void* d_out, int out_size) {
    const float* h    = (const float*)d_in[0];   // [100000,192]
    const float* Wout = (const float*)d_in[1];   // [192,1]
    const int*   src  = (const int*)d_in[2];     // [36,30000]
    const int*   seg  = (const int*)d_in[3];     // [36,30000]
    const int*   mask = (const int*)d_in[4];     // [256,36] bool -> int32
    float*       out  = (float*)d_out;           // [256,36]

    dot_kernel<<<(N_BOND + 31) / 32, 256>>>(h, Wout, src, seg);
    edge_kernel<<<EDGE_BLOCKS, 256>>>(src, seg, mask, out);
}

// round 9
// speedup vs baseline: 1.6817x; 1.6817x over previous
#include <cuda_runtime.h>
#include <cuda_bf16.h>

#define N_BOND   100000
#define D        192
#define N_ETYPES 36
#define E_PER_T  30000
#define BATCH    256
#define N_EDGES  (N_ETYPES * E_PER_T)   // 1,080,000
#define N_SEG    (N_ETYPES * BATCH)     // 9216
#define N_PACKS  (N_EDGES / 4)          // 270000

__device__ float g_s[N_BOND];     // per-node scalar projection h[i,:] . W_out
__device__ float g_acc[N_SEG];    // segment accumulators [type*BATCH + graph]

// ---------------------------------------------------------------------------
// Kernel 1: s[row] = dot(h[row,:], W_out).  Measured-best shape (R4):
// half-warp per row, 4 rows per warp, 6 LDG.128 in flight, one-shot blocks.
// Side jobs: zero g_acc; L2-prefetch src/seg for edge_kernel.
// ---------------------------------------------------------------------------
__global__ void dot_kernel(const float* __restrict__ h,
                           const float* __restrict__ W,
                           const int*   __restrict__ src,
                           const int*   __restrict__ seg) {
    const int tid = blockIdx.x * blockDim.x + threadIdx.x;
    if (tid < N_SEG) g_acc[tid] = 0.f;

    // Warm L2 with the edge index arrays (8.6 MB; L2 = 126 MB).
    {
        const int nlines = (N_EDGES * 4) / 128;   // 33750 lines per array
        if (tid < nlines) {
            asm volatile("prefetch.global.L2 [%0];" ::
                         "l"((const char*)src + (size_t)tid * 128));
            asm volatile("prefetch.global.L2 [%0];" ::
                         "l"((const char*)seg + (size_t)tid * 128));
        }
    }

    const int lane = threadIdx.x & 31;
    const int half = lane >> 4;           // 0 or 1
    const int hl   = lane & 15;           // lane within half-warp
    const int warp = tid >> 5;

    const float4* W4 = reinterpret_cast<const float4*>(W);
    const float4 w0 = W4[hl];
    const float4 w1 = W4[16 + hl];
    const float4 w2 = W4[32 + hl];

    const int row0 = 4 * warp + half;
    const int row1 = row0 + 2;
    if (row0 >= N_BOND) return;

    const float4* p0 = reinterpret_cast<const float4*>(h + (size_t)row0 * D);
    const float4* p1 = reinterpret_cast<const float4*>(h + (size_t)row1 * D);
    float4 a0 = __ldcs(p0 + hl), b0 = __ldcs(p0 + 16 + hl), c0 = __ldcs(p0 + 32 + hl);
    float4 a1 = __ldcs(p1 + hl), b1 = __ldcs(p1 + 16 + hl), c1 = __ldcs(p1 + 32 + hl);

    float acc0 = a0.x * w0.x + a0.y * w0.y + a0.z * w0.z + a0.w * w0.w
               + b0.x * w1.x + b0.y * w1.y + b0.z * w1.z + b0.w * w1.w
               + c0.x * w2.x + c0.y * w2.y + c0.z * w2.z + c0.w * w2.w;
    float acc1 = a1.x * w0.x + a1.y * w0.y + a1.z * w0.z + a1.w * w0.w
               + b1.x * w1.x + b1.y * w1.y + b1.z * w1.z + b1.w * w1.w
               + c1.x * w2.x + c1.y * w2.y + c1.z * w2.z + c1.w * w2.w;

    #pragma unroll
    for (int off = 8; off > 0; off >>= 1) {
        acc0 += __shfl_down_sync(0xffffffffu, acc0, off, 16);
        acc1 += __shfl_down_sync(0xffffffffu, acc1, off, 16);
    }
    if (hl == 0) {
        g_s[row0] = acc0;
        g_s[row1] = acc1;
    }
}

// ---------------------------------------------------------------------------
// Kernel 2: 4 edges per thread (int4), intra-thread run compaction, then
// warp-level segmented reduction over sorted keys, atomicAdd per run head.
// src/seg are L2-resident thanks to the prefetch in dot_kernel.
// ---------------------------------------------------------------------------
__global__ void edge_kernel(const int* __restrict__ src,
                            const int* __restrict__ seg) {
    const int idx  = blockIdx.x * blockDim.x + threadIdx.x;   // pack index
    const int lane = threadIdx.x & 31;

    float val = 0.f;
    int   key = -1;
    if (idx < N_PACKS) {
        const int e0 = idx * 4;
        const int t  = e0 / E_PER_T;     // 4 | 30000: pack never crosses a type
        int4 s4 = reinterpret_cast<const int4*>(src)[idx];
        int4 g4 = reinterpret_cast<const int4*>(seg)[idx];

        float v0 = g_s[s4.x], v1 = g_s[s4.y], v2 = g_s[s4.z], v3 = g_s[s4.w];
        const int kb = t * BATCH;
        int k0 = kb + g4.x, k1 = kb + g4.y, k2 = kb + g4.z, k3 = kb + g4.w;

        float acc = v0; int cur = k0;
        if (k1 == cur) acc += v1; else { atomicAdd(&g_acc[cur], acc); cur = k1; acc = v1; }
        if (k2 == cur) acc += v2; else { atomicAdd(&g_acc[cur], acc); cur = k2; acc = v2; }
        if (k3 == cur) acc += v3; else { atomicAdd(&g_acc[cur], acc); cur = k3; acc = v3; }
        val = acc; key = cur;
    }

    #pragma unroll
    for (int off = 1; off < 32; off <<= 1) {
        int   okey = __shfl_down_sync(0xffffffffu, key, off);
        float oval = __shfl_down_sync(0xffffffffu, val, off);
        if (lane + off < 32 && okey == key) val += oval;
    }
    int pkey = __shfl_up_sync(0xffffffffu, key, 1);
    if (((lane == 0) || (pkey != key)) && key >= 0) atomicAdd(&g_acc[key], val);
}

// ---------------------------------------------------------------------------
// Kernel 3: mask + softmax. 36 threads/graph, 8 graphs/block, 32 blocks.
// ---------------------------------------------------------------------------
__global__ void softmax_kernel(const int* __restrict__ mask,
                               float* __restrict__ out) {
    __shared__ float sv[8][N_ETYPES];
    __shared__ float sred[8];

    const int g = threadIdx.x / N_ETYPES;
    const int t = threadIdx.x % N_ETYPES;
    const int b = blockIdx.x * 8 + g;

    float x = g_acc[t * BATCH + b];
    if (mask[b * N_ETYPES + t] != 0) x = -1e9f;
    sv[g][t] = x;
    __syncthreads();

    if (t == 0) {
        float mx = sv[g][0];
        #pragma unroll
        for (int i = 1; i < N_ETYPES; i++) mx = fmaxf(mx, sv[g][i]);
        sred[g] = mx;
    }
    __syncthreads();

    float e = __expf(x - sred[g]);
    sv[g][t] = e;
    __syncthreads();

    if (t == 0) {
        float s = 0.f;
        #pragma unroll
        for (int i = 0; i < N_ETYPES; i++) s += sv[g][i];
        sred[g] = s;
    }
    __syncthreads();

    out[b * N_ETYPES + t] = e / sred[g];
}

// ---------------------------------------------------------------------------
extern "C" void kernel_launch(void* const* d_in, const int* in_sizes, int n_in,
                              void* d_out, int out_size) {
    const float* h    = (const float*)d_in[0];   // [100000,192]
    const float* Wout = (const float*)d_in[1];   // [192,1]
    const int*   src  = (const int*)d_in[2];     // [36,30000]
    const int*   seg  = (const int*)d_in[3];     // [36,30000]
    const int*   mask = (const int*)d_in[4];     // [256,36] bool -> int32
    float*       out  = (float*)d_out;           // [256,36]

    dot_kernel<<<(N_BOND + 31) / 32, 256>>>(h, Wout, src, seg);
    edge_kernel<<<(N_PACKS + 255) / 256, 256>>>(src, seg);
    softmax_kernel<<<BATCH / 8, 8 * N_ETYPES>>>(mask, out);
}

// round 10
// speedup vs baseline: 1.7044x; 1.0135x over previous
#include <cuda_runtime.h>
#include <cuda_bf16.h>

#define N_BOND   100000
#define D        192
#define N_ETYPES 36
#define E_PER_T  30000
#define BATCH    256
#define N_EDGES  (N_ETYPES * E_PER_T)   // 1,080,000
#define N_SEG    (N_ETYPES * BATCH)     // 9216
#define N_OCT    (N_EDGES / 8)          // 135000 packs of 8 (8 | 30000)

__device__ float g_s[N_BOND];     // per-node scalar projection h[i,:] . W_out
__device__ float g_acc[N_SEG];    // segment accumulators [type*BATCH + graph]

// ---------------------------------------------------------------------------
// Kernel 1: s[row] = dot(h[row,:], W_out).  Exact R4 shape (measured 15.7us):
// half-warp per row, 4 rows per warp, 6 LDG.128 in flight, one-shot blocks.
// Also zeroes g_acc (completes before edge_kernel).
// ---------------------------------------------------------------------------
__global__ void dot_kernel(const float* __restrict__ h,
                           const float* __restrict__ W) {
    const int tid = blockIdx.x * blockDim.x + threadIdx.x;
    if (tid < N_SEG) g_acc[tid] = 0.f;

    const int lane = threadIdx.x & 31;
    const int half = lane >> 4;           // 0 or 1
    const int hl   = lane & 15;           // lane within half-warp
    const int warp = tid >> 5;

    const float4* W4 = reinterpret_cast<const float4*>(W);
    const float4 w0 = W4[hl];
    const float4 w1 = W4[16 + hl];
    const float4 w2 = W4[32 + hl];

    const int row0 = 4 * warp + half;
    const int row1 = row0 + 2;
    if (row0 >= N_BOND) return;

    const float4* p0 = reinterpret_cast<const float4*>(h + (size_t)row0 * D);
    const float4* p1 = reinterpret_cast<const float4*>(h + (size_t)row1 * D);
    float4 a0 = p0[hl], b0 = p0[16 + hl], c0 = p0[32 + hl];
    float4 a1 = p1[hl], b1 = p1[16 + hl], c1 = p1[32 + hl];

    float acc0 = a0.x * w0.x + a0.y * w0.y + a0.z * w0.z + a0.w * w0.w
               + b0.x * w1.x + b0.y * w1.y + b0.z * w1.z + b0.w * w1.w
               + c0.x * w2.x + c0.y * w2.y + c0.z * w2.z + c0.w * w2.w;
    float acc1 = a1.x * w0.x + a1.y * w0.y + a1.z * w0.z + a1.w * w0.w
               + b1.x * w1.x + b1.y * w1.y + b1.z * w1.z + b1.w * w1.w
               + c1.x * w2.x + c1.y * w2.y + c1.z * w2.z + c1.w * w2.w;

    #pragma unroll
    for (int off = 8; off > 0; off >>= 1) {
        acc0 += __shfl_down_sync(0xffffffffu, acc0, off, 16);
        acc1 += __shfl_down_sync(0xffffffffu, acc1, off, 16);
    }
    if (hl == 0) {
        g_s[row0] = acc0;
        g_s[row1] = acc1;
    }
}

// ---------------------------------------------------------------------------
// Kernel 2: 8 edges per thread (2x int4 per array -> 4 independent loads in
// flight), intra-thread run compaction over the 8 sorted keys, then warp
// segmented reduction over tail runs, atomicAdd per run head.
// 8 | 30000 so an 8-pack never crosses a type boundary.
// ---------------------------------------------------------------------------
__global__ void edge_kernel(const int* __restrict__ src,
                            const int* __restrict__ seg) {
    const int idx  = blockIdx.x * blockDim.x + threadIdx.x;   // oct index
    const int lane = threadIdx.x & 31;

    float val = 0.f;
    int   key = -1;
    if (idx < N_OCT) {
        const int e0 = idx * 8;
        const int t  = e0 / E_PER_T;
        const int4* s4p = reinterpret_cast<const int4*>(src) + idx * 2;
        const int4* g4p = reinterpret_cast<const int4*>(seg) + idx * 2;
        int4 sA = s4p[0], sB = s4p[1];
        int4 gA = g4p[0], gB = g4p[1];

        float v[8];
        v[0] = g_s[sA.x]; v[1] = g_s[sA.y]; v[2] = g_s[sA.z]; v[3] = g_s[sA.w];
        v[4] = g_s[sB.x]; v[5] = g_s[sB.y]; v[6] = g_s[sB.z]; v[7] = g_s[sB.w];

        const int kb = t * BATCH;
        int k[8];
        k[0] = kb + gA.x; k[1] = kb + gA.y; k[2] = kb + gA.z; k[3] = kb + gA.w;
        k[4] = kb + gB.x; k[5] = kb + gB.y; k[6] = kb + gB.z; k[7] = kb + gB.w;

        float acc = v[0]; int cur = k[0];
        #pragma unroll
        for (int j = 1; j < 8; j++) {
            if (k[j] == cur) acc += v[j];
            else { atomicAdd(&g_acc[cur], acc); cur = k[j]; acc = v[j]; }
        }
        val = acc; key = cur;   // tail run continues into warp stage
    }

    // Segmented inclusive reduction over sorted tail-run keys.
    #pragma unroll
    for (int off = 1; off < 32; off <<= 1) {
        int   okey = __shfl_down_sync(0xffffffffu, key, off);
        float oval = __shfl_down_sync(0xffffffffu, val, off);
        if (lane + off < 32 && okey == key) val += oval;
    }
    int pkey = __shfl_up_sync(0xffffffffu, key, 1);
    if (((lane == 0) || (pkey != key)) && key >= 0) atomicAdd(&g_acc[key], val);
}

// ---------------------------------------------------------------------------
// Kernel 3: mask + softmax. 36 threads/graph, 8 graphs/block, 32 blocks.
// ---------------------------------------------------------------------------
__global__ void softmax_kernel(const int* __restrict__ mask,
                               float* __restrict__ out) {
    __shared__ float sv[8][N_ETYPES];
    __shared__ float sred[8];

    const int g = threadIdx.x / N_ETYPES;
    const int t = threadIdx.x % N_ETYPES;
    const int b = blockIdx.x * 8 + g;

    float x = g_acc[t * BATCH + b];
    if (mask[b * N_ETYPES + t] != 0) x = -1e9f;
    sv[g][t] = x;
    __syncthreads();

    if (t == 0) {
        float mx = sv[g][0];
        #pragma unroll
        for (int i = 1; i < N_ETYPES; i++) mx = fmaxf(mx, sv[g][i]);
        sred[g] = mx;
    }
    __syncthreads();

    float e = __expf(x - sred[g]);
    sv[g][t] = e;
    __syncthreads();

    if (t == 0) {
        float s = 0.f;
        #pragma unroll
        for (int i = 0; i < N_ETYPES; i++) s += sv[g][i];
        sred[g] = s;
    }
    __syncthreads();

    out[b * N_ETYPES + t] = e / sred[g];
}

// ---------------------------------------------------------------------------
extern "C" void kernel_launch(void* const* d_in, const int* in_sizes, int n_in,
                              void* d_out, int out_size) {
    const float* h    = (const float*)d_in[0];   // [100000,192]
    const float* Wout = (const float*)d_in[1];   // [192,1]
    const int*   src  = (const int*)d_in[2];     // [36,30000]
    const int*   seg  = (const int*)d_in[3];     // [36,30000]
    const int*   mask = (const int*)d_in[4];     // [256,36] bool -> int32
    float*       out  = (float*)d_out;           // [256,36]

    dot_kernel<<<(N_BOND + 31) / 32, 256>>>(h, Wout);          // + g_acc zeroing
    edge_kernel<<<(N_OCT + 255) / 256, 256>>>(src, seg);
    softmax_kernel<<<BATCH / 8, 8 * N_ETYPES>>>(mask, out);
}